// round 15
// baseline (speedup 1.0000x reference)
#include <cuda_runtime.h>
#include <cstdint>

#define D_MODEL     2048
#define NUM_EXPERTS 64
#define TOP_K       4
#define TM          16               // tokens per CTA
#define KC          32               // K chunk
#define NCHUNK      (D_MODEL / KC)   // 64
#define N_TOKENS    16384
#define NBLK        (N_TOKENS / TM)  // 1024

#define AROWB       144              // A row stride bytes (32 floats + 4 pad)
#define A_STAGE_B   (TM * AROWB)     // 2304 B
#define BROWB       272              // B k-row stride bytes (32 pairs + 2 pad ULL)
#define B_STAGE_B   (KC * BROWB)     // 8704 B
#define B_OFF       (2 * A_STAGE_B)  // 4608
#define SBUF_BYTES  (B_OFF + 2 * B_STAGE_B)   // 22016

__device__ float g_expert_partial[NBLK * NUM_EXPERTS];
__device__ int   g_done;             // zero-init; reset by last CTA each run

__device__ __forceinline__ uint32_t smem_to_u32(const void* p) {
    uint32_t a;
    asm("{ .reg .u64 t; cvta.to.shared.u64 t, %1; cvt.u32.u64 %0, t; }" : "=r"(a) : "l"(p));
    return a;
}
#define CP_ASYNC16(dst_u32, src_ptr) \
    asm volatile("cp.async.cg.shared.global [%0], [%1], 16;" :: "r"(dst_u32), "l"(src_ptr))
#define CP_COMMIT() asm volatile("cp.async.commit_group;" ::: "memory")
#define CP_WAIT1()  asm volatile("cp.async.wait_group 1;" ::: "memory")
#define CP_WAIT0()  asm volatile("cp.async.wait_group 0;" ::: "memory")

__device__ __forceinline__ void fma2(unsigned long long& d, unsigned long long a, unsigned long long b) {
    asm("fma.rn.f32x2 %0, %1, %2, %0;" : "+l"(d) : "l"(a), "l"(b));
}
__device__ __forceinline__ unsigned long long dup2(float x) {
    unsigned long long r;
    uint32_t xb = __float_as_uint(x);
    asm("mov.b64 %0, {%1, %1};" : "=l"(r) : "r"(xb));
    return r;
}
__device__ __forceinline__ void unpack2(unsigned long long v, float& lo, float& hi) {
    uint32_t l, h;
    asm("mov.b64 {%0, %1}, %2;" : "=r"(l), "=r"(h) : "l"(v));
    lo = __uint_as_float(l); hi = __uint_as_float(h);
}

__global__ void __launch_bounds__(64, 8) router_kernel(
    const float* __restrict__ u, const float* __restrict__ E,
    const float* __restrict__ bias,
    float* __restrict__ out_idx, float* __restrict__ out_val,
    float* __restrict__ out_scores, float* __restrict__ out_aux)
{
    __shared__ __align__(16) char sbuf[SBUF_BYTES];
    __shared__ float biasS[NUM_EXPERTS];
    __shared__ float sq[NUM_EXPERTS];
    __shared__ int   lastFlag;

    const uint32_t sb = smem_to_u32(sbuf);
    const int tid = threadIdx.x, lid = tid & 31, wid = tid >> 5;
    const int tg = lid & 7;                 // tokens tg, tg+8
    const int pg = lid >> 3;                // 0..3
    const int pb = (wid * 4 + pg) * 4;      // pairs pb..pb+3 (experts 2pb..2pb+7)
    const int tokBase = blockIdx.x * TM;

    if (tid == 0) lastFlag = 0;
    biasS[tid] = bias[tid];                 // 64 threads -> all 64 experts

    auto issue = [&](int c) {
        const int st = c & 1;
        const int k0 = c * KC;
        const uint32_t ab = sb + st * A_STAGE_B;
        const uint32_t bb = sb + B_OFF + st * B_STAGE_B;
        // A: 16 rows x 8 x 16B = 128 units, 2/thread
#pragma unroll
        for (int i = 0; i < 2; i++) {
            int unit = tid + 64 * i;
            int row = unit >> 3, off = unit & 7;
            CP_ASYNC16(ab + (uint32_t)(row * AROWB + off * 16),
                       u + (size_t)(tokBase + row) * D_MODEL + k0 + off * 4);
        }
        // B: raw E rows k0..k0+31: 32 rows x 16 units = 512 units, 8/thread
#pragma unroll
        for (int i = 0; i < 8; i++) {
            int unit = tid + 64 * i;
            int kr = unit >> 4, off = unit & 15;
            CP_ASYNC16(bb + (uint32_t)(kr * BROWB + off * 16),
                       E + (size_t)(k0 + kr) * NUM_EXPERTS + off * 4);
        }
        CP_COMMIT();
    };

    unsigned long long acc[2][4];           // [token][pair j] f32x2
#pragma unroll
    for (int i = 0; i < 2; i++)
#pragma unroll
        for (int j = 0; j < 4; j++) acc[i][j] = 0ull;

    issue(0);
    issue(1);

    for (int c = 0; c < NCHUNK; c++) {
        if (c < NCHUNK - 1) CP_WAIT1(); else CP_WAIT0();
        __syncthreads();

        const int st = c & 1;
        const char* aB = sbuf + st * A_STAGE_B;
        const char* bB = sbuf + B_OFF + st * B_STAGE_B;

#pragma unroll
        for (int kq = 0; kq < KC / 4; kq++) {
            // A: one LDS128 per token -> 4 k-steps
            float4 a0 = *reinterpret_cast<const float4*>(aB + tg * AROWB + kq * 16);
            float4 a1 = *reinterpret_cast<const float4*>(aB + (tg + 8) * AROWB + kq * 16);
            const float* a0f = reinterpret_cast<const float*>(&a0);
            const float* a1f = reinterpret_cast<const float*>(&a1);
#pragma unroll
            for (int dk = 0; dk < 4; dk++) {
                const int k = kq * 4 + dk;
                // B: two LDS128 = 4 pairs for this k
                ulonglong2 b01 = *reinterpret_cast<const ulonglong2*>(bB + k * BROWB + pb * 8);
                ulonglong2 b23 = *reinterpret_cast<const ulonglong2*>(bB + k * BROWB + pb * 8 + 16);
                unsigned long long av0 = dup2(a0f[dk]);
                unsigned long long av1 = dup2(a1f[dk]);
                fma2(acc[0][0], av0, b01.x);
                fma2(acc[0][1], av0, b01.y);
                fma2(acc[0][2], av0, b23.x);
                fma2(acc[0][3], av0, b23.y);
                fma2(acc[1][0], av1, b01.x);
                fma2(acc[1][1], av1, b01.y);
                fma2(acc[1][2], av1, b23.x);
                fma2(acc[1][3], av1, b23.y);
            }
        }
        __syncthreads();
        if (c + 2 < NCHUNK) issue(c + 2);
    }

    // ---- epilogue: acc -> L[16][65] (overlays A region; 4160 <= 4608) ----
    float* L = (float*)sbuf;
#pragma unroll
    for (int i = 0; i < 2; i++) {
        const int t = tg + 8 * i;
#pragma unroll
        for (int j = 0; j < 4; j++) {
            const int e0 = 2 * (pb + j);
            float lo, hi;
            unpack2(acc[i][j], lo, hi);
            L[t * 65 + e0]     = lo;
            L[t * 65 + e0 + 1] = hi;
        }
    }
    __syncthreads();

    if (tid < TM) {
        const int t = tid;
        float p[64];
        float mx = -1e30f;
#pragma unroll
        for (int e = 0; e < 64; e++) { p[e] = L[t * 65 + e] + biasS[e]; mx = fmaxf(mx, p[e]); }
        float s = 0.f;
#pragma unroll
        for (int e = 0; e < 64; e++) { p[e] = expf(p[e] - mx); s += p[e]; }
        const float inv = 1.f / s;
#pragma unroll
        for (int e = 0; e < 64; e++) p[e] *= inv;

        const int gtok = tokBase + t;
        unsigned long long chosen = 0ull;
#pragma unroll
        for (int r = 0; r < TOP_K; r++) {
            float bv = -1.f; int bi = 0;
#pragma unroll
            for (int e = 0; e < 64; e++) {
                bool skip = (chosen >> e) & 1ull;
                if (!skip && p[e] > bv) { bv = p[e]; bi = e; }  // strict >: lowest idx ties
            }
            chosen |= 1ull << bi;
            out_idx[(size_t)gtok * TOP_K + r] = (float)bi;
            out_val[(size_t)gtok * TOP_K + r] = bv;
        }
#pragma unroll
        for (int e = 0; e < 64; e++) L[t * 65 + e] = p[e];
    }
    __syncthreads();

    // coalesced scores writeback: 1024 floats, 16/thread
#pragma unroll
    for (int i = 0; i < 16; i++) {
        int idx = tid + i * 64;
        int t = idx >> 6, e = idx & 63;
        out_scores[(size_t)(tokBase + t) * NUM_EXPERTS + e] = L[t * 65 + e];
    }
    // deterministic per-block expert sums (tid = expert)
    {
        float s = 0.f;
#pragma unroll
        for (int t = 0; t < TM; t++) s += L[t * 65 + tid];
        g_expert_partial[(size_t)blockIdx.x * NUM_EXPERTS + tid] = s;
    }

    // ---- elected-last-CTA aux reduction (fixed-order, deterministic) ----
    __threadfence();
    if (tid == 0) lastFlag = (atomicAdd(&g_done, 1) == NBLK - 1) ? 1 : 0;
    __syncthreads();
    if (lastFlag) {
        const int e = tid;                       // 64 threads, one expert each
        float s0 = 0.f, s1 = 0.f, s2 = 0.f, s3 = 0.f;
#pragma unroll 4
        for (int b = 0; b < NBLK; b += 4) {      // fixed interleaved grouping: deterministic
            s0 += g_expert_partial[(size_t)(b + 0) * NUM_EXPERTS + e];
            s1 += g_expert_partial[(size_t)(b + 1) * NUM_EXPERTS + e];
            s2 += g_expert_partial[(size_t)(b + 2) * NUM_EXPERTS + e];
            s3 += g_expert_partial[(size_t)(b + 3) * NUM_EXPERTS + e];
        }
        float m = ((s0 + s1) + (s2 + s3)) * (1.f / (float)N_TOKENS);
        sq[e] = m * m;
        __syncthreads();
        if (tid == 0) {
            float a = 0.f;
#pragma unroll
            for (int k = 0; k < 64; k++) a += sq[k];
            out_aux[0] = a * (float)NUM_EXPERTS;
            g_done = 0;                          // reset for next replay
        }
    }
}

extern "C" void kernel_launch(void* const* d_in, const int* in_sizes, int n_in,
                              void* d_out, int out_size)
{
    const float* u    = (const float*)d_in[0];
    const float* E    = (const float*)d_in[1];
    const float* bias = (const float*)d_in[2];

    float* out        = (float*)d_out;
    float* out_idx    = out;
    float* out_val    = out_idx + (size_t)N_TOKENS * TOP_K;
    float* out_scores = out_val + (size_t)N_TOKENS * TOP_K;
    float* out_aux    = out_scores + (size_t)N_TOKENS * NUM_EXPERTS;

    router_kernel<<<NBLK, 64>>>(u, E, bias, out_idx, out_val, out_scores, out_aux);
}

// round 16
// speedup vs baseline: 1.0554x; 1.0554x over previous
#include <cuda_runtime.h>
#include <cstdint>

#define D_MODEL     2048
#define NUM_EXPERTS 64
#define TOP_K       4
#define TM          16               // tokens per CTA
#define KC          16               // K chunk
#define NCHUNK      (D_MODEL / KC)   // 128
#define N_TOKENS    16384
#define NBLK        (N_TOKENS / TM)  // 1024

#define AROWB       144              // A token-row stride bytes (16 k * 8B dup + 16 pad)
#define A_STAGE_B   (TM * AROWB)     // 2304
#define BROWB       288              // B k-row stride bytes (256 data + 32 pad)
#define B_STAGE_B   (KC * BROWB)     // 4608
#define B_OFF       (2 * A_STAGE_B)  // 4608
#define SBUF_BYTES  (B_OFF + 2 * B_STAGE_B)   // 13824

__device__ float g_expert_partial[NBLK * NUM_EXPERTS];

__device__ __forceinline__ uint32_t smem_to_u32(const void* p) {
    uint32_t a;
    asm("{ .reg .u64 t; cvta.to.shared.u64 t, %1; cvt.u32.u64 %0, t; }" : "=r"(a) : "l"(p));
    return a;
}
#define CP_ASYNC16(dst_u32, src_ptr) \
    asm volatile("cp.async.cg.shared.global [%0], [%1], 16;" :: "r"(dst_u32), "l"(src_ptr))
#define CP_COMMIT() asm volatile("cp.async.commit_group;" ::: "memory")
#define CP_WAIT1()  asm volatile("cp.async.wait_group 1;" ::: "memory")
#define CP_WAIT0()  asm volatile("cp.async.wait_group 0;" ::: "memory")

__device__ __forceinline__ void fma2(unsigned long long& d, unsigned long long a, unsigned long long b) {
    asm("fma.rn.f32x2 %0, %1, %2, %0;" : "+l"(d) : "l"(a), "l"(b));
}
__device__ __forceinline__ void unpack2(unsigned long long v, float& lo, float& hi) {
    uint32_t l, h;
    asm("mov.b64 {%0, %1}, %2;" : "=r"(l), "=r"(h) : "l"(v));
    lo = __uint_as_float(l); hi = __uint_as_float(h);
}
// store (x,x,y,y) — pre-duplicated A pair for two consecutive k
#define STS_DUP4(addr, x, y) \
    asm volatile("st.shared.v4.f32 [%0], {%1, %1, %2, %2};" :: "r"(addr), "f"(x), "f"(y) : "memory")

__global__ void __launch_bounds__(32, 16) router_kernel(
    const float* __restrict__ u, const float* __restrict__ E,
    const float* __restrict__ bias,
    float* __restrict__ out_idx, float* __restrict__ out_val,
    float* __restrict__ out_scores)
{
    __shared__ __align__(16) char sbuf[SBUF_BYTES];
    __shared__ float biasS[NUM_EXPERTS];

    const uint32_t sb = smem_to_u32(sbuf);
    const int tid = threadIdx.x;
    const int ts = tid & 3;              // token slot: tokens ts + 4i
    const int ps = tid >> 2;             // 0..7: pairs {2ps, 2ps+1, 2ps+16, 2ps+17}
    const int tokBase = blockIdx.x * TM;

    biasS[tid] = bias[tid];
    biasS[tid + 32] = bias[tid + 32];

    // ---- A fill: LDG 8 floats -> regs ; STS pre-duplicated quads ----
    const int atok = tid >> 1;           // 0..15
    const int akh  = tid & 1;            // k-half (8 k's)
    float4 vbuf[2];
    auto ldgA = [&](int c) {
        const float* src = u + (size_t)(tokBase + atok) * D_MODEL + c * KC + akh * 8;
        vbuf[0] = *reinterpret_cast<const float4*>(src);
        vbuf[1] = *reinterpret_cast<const float4*>(src + 4);
    };
    auto stsA = [&](int c) {
        const int st = c & 1;
        const uint32_t base = sb + st * A_STAGE_B + atok * AROWB + akh * 64;
        const float* f = reinterpret_cast<const float*>(vbuf);
#pragma unroll
        for (int q = 0; q < 4; q++)
            STS_DUP4(base + q * 16, f[2 * q], f[2 * q + 1]);
    };
    auto cpB = [&](int c) {
        const int st = c & 1;
        const uint32_t bb = sb + B_OFF + st * B_STAGE_B;
#pragma unroll
        for (int i = 0; i < 8; i++) {
            int unit = tid + 32 * i;          // 256 units: 16 rows x 16
            int row = unit >> 4, off = unit & 15;
            CP_ASYNC16(bb + (uint32_t)(row * BROWB + off * 16),
                       E + (size_t)(c * KC + row) * NUM_EXPERTS + off * 4);
        }
        CP_COMMIT();
    };

    unsigned long long acc[4][4];
#pragma unroll
    for (int i = 0; i < 4; i++)
#pragma unroll
        for (int j = 0; j < 4; j++) acc[i][j] = 0ull;

    // prologue
    ldgA(0); stsA(0); cpB(0);
    ldgA(1); stsA(1); cpB(1);
    ldgA(2);

    for (int c = 0; c < NCHUNK; c++) {
        if (c < NCHUNK - 2) CP_WAIT1(); else CP_WAIT0();
        __syncwarp();

        const int st = c & 1;
        const char* aB = sbuf + st * A_STAGE_B;
        const char* bB = sbuf + B_OFF + st * B_STAGE_B;

#pragma unroll
        for (int kq = 0; kq < KC / 2; kq++) {
            ulonglong2 av[4];
#pragma unroll
            for (int i = 0; i < 4; i++)
                av[i] = *reinterpret_cast<const ulonglong2*>(aB + (ts + 4 * i) * AROWB + kq * 16);
#pragma unroll
            for (int dk = 0; dk < 2; dk++) {
                const int k = kq * 2 + dk;
                ulonglong2 b01 = *reinterpret_cast<const ulonglong2*>(bB + k * BROWB + ps * 16);
                ulonglong2 b23 = *reinterpret_cast<const ulonglong2*>(bB + k * BROWB + ps * 16 + 128);
#pragma unroll
                for (int i = 0; i < 4; i++) {
                    unsigned long long a = dk ? av[i].y : av[i].x;  // pre-duplicated
                    fma2(acc[i][0], a, b01.x);
                    fma2(acc[i][1], a, b01.y);
                    fma2(acc[i][2], a, b23.x);
                    fma2(acc[i][3], a, b23.y);
                }
            }
        }
        __syncwarp();
        if (c + 2 < NCHUNK) { stsA(c + 2); cpB(c + 2); }
        if (c + 3 < NCHUNK) ldgA(c + 3);
    }

    // ---- epilogue: acc -> L[16][65] (overlays A region; 4160 <= 4608) ----
    float* L = (float*)sbuf;
    __syncwarp();
#pragma unroll
    for (int i = 0; i < 4; i++) {
        const int t = ts + 4 * i;
        float lo, hi;
        unpack2(acc[i][0], lo, hi); L[t * 65 + 4 * ps]      = lo; L[t * 65 + 4 * ps + 1]  = hi;
        unpack2(acc[i][1], lo, hi); L[t * 65 + 4 * ps + 2]  = lo; L[t * 65 + 4 * ps + 3]  = hi;
        unpack2(acc[i][2], lo, hi); L[t * 65 + 4 * ps + 32] = lo; L[t * 65 + 4 * ps + 33] = hi;
        unpack2(acc[i][3], lo, hi); L[t * 65 + 4 * ps + 34] = lo; L[t * 65 + 4 * ps + 35] = hi;
    }
    __syncwarp();

    if (tid < TM) {
        const int t = tid;
        float p[64];
        float mx = -1e30f;
#pragma unroll
        for (int e = 0; e < 64; e++) { p[e] = L[t * 65 + e] + biasS[e]; mx = fmaxf(mx, p[e]); }
        float s = 0.f;
#pragma unroll
        for (int e = 0; e < 64; e++) { p[e] = expf(p[e] - mx); s += p[e]; }
        const float inv = 1.f / s;
#pragma unroll
        for (int e = 0; e < 64; e++) p[e] *= inv;

        const int gtok = tokBase + t;
        unsigned long long chosen = 0ull;
#pragma unroll
        for (int r = 0; r < TOP_K; r++) {
            float bv = -1.f; int bi = 0;
#pragma unroll
            for (int e = 0; e < 64; e++) {
                bool skip = (chosen >> e) & 1ull;
                if (!skip && p[e] > bv) { bv = p[e]; bi = e; }  // strict >: lowest idx ties
            }
            chosen |= 1ull << bi;
            out_idx[(size_t)gtok * TOP_K + r] = (float)bi;
            out_val[(size_t)gtok * TOP_K + r] = bv;
        }
#pragma unroll
        for (int e = 0; e < 64; e++) L[t * 65 + e] = p[e];
    }
    __syncwarp();

    // coalesced scores writeback: 1024 floats, 32/thread
#pragma unroll
    for (int i = 0; i < 32; i++) {
        int idx = tid + i * 32;
        int t = idx >> 6, e = idx & 63;
        out_scores[(size_t)(tokBase + t) * NUM_EXPERTS + e] = L[t * 65 + e];
    }
    // per-block expert sums (2 experts per thread)
#pragma unroll
    for (int h = 0; h < 2; h++) {
        const int e = tid + 32 * h;
        float s = 0.f;
#pragma unroll
        for (int t = 0; t < TM; t++) s += L[t * 65 + e];
        g_expert_partial[(size_t)blockIdx.x * NUM_EXPERTS + e] = s;
    }
}

// ================= aux loss reduction (order-free: 1e-3 tolerance) ==========
__global__ void aux_kernel(float* __restrict__ out_aux) {
    __shared__ float red[16][NUM_EXPERTS + 1];
    __shared__ float sq[NUM_EXPERTS];
    const int tid = threadIdx.x;            // 1024 threads
    const int e = tid & 63, g = tid >> 6;   // 16 groups x 64 experts
    float s0 = 0.f, s1 = 0.f, s2 = 0.f, s3 = 0.f;
    const int b0 = g * (NBLK / 16);
#pragma unroll 4
    for (int b = 0; b < NBLK / 16; b += 4) {   // 64 blocks per group, 4 ILP chains
        s0 += g_expert_partial[(size_t)(b0 + b + 0) * NUM_EXPERTS + e];
        s1 += g_expert_partial[(size_t)(b0 + b + 1) * NUM_EXPERTS + e];
        s2 += g_expert_partial[(size_t)(b0 + b + 2) * NUM_EXPERTS + e];
        s3 += g_expert_partial[(size_t)(b0 + b + 3) * NUM_EXPERTS + e];
    }
    red[g][e] = (s0 + s1) + (s2 + s3);
    __syncthreads();
    if (tid < 64) {
        float t = 0.f;
#pragma unroll
        for (int k = 0; k < 16; k++) t += red[k][tid];
        float m = t * (1.f / (float)N_TOKENS);
        sq[tid] = m * m;
    }
    __syncthreads();
    if (tid == 0) {
        float a = 0.f;
#pragma unroll
        for (int k = 0; k < 64; k++) a += sq[k];
        out_aux[0] = a * (float)NUM_EXPERTS;
    }
}

extern "C" void kernel_launch(void* const* d_in, const int* in_sizes, int n_in,
                              void* d_out, int out_size)
{
    const float* u    = (const float*)d_in[0];
    const float* E    = (const float*)d_in[1];
    const float* bias = (const float*)d_in[2];

    float* out        = (float*)d_out;
    float* out_idx    = out;
    float* out_val    = out_idx + (size_t)N_TOKENS * TOP_K;
    float* out_scores = out_val + (size_t)N_TOKENS * TOP_K;
    float* out_aux    = out_scores + (size_t)N_TOKENS * NUM_EXPERTS;

    router_kernel<<<NBLK, 32>>>(u, E, bias, out_idx, out_val, out_scores);
    aux_kernel<<<1, 1024>>>(out_aux);
}